// round 9
// baseline (speedup 1.0000x reference)
#include <cuda_runtime.h>
#include <math.h>

#define T_LEN  1024
#define D_DIM  256
#define K_CH   4
#define NCHUNK 128
#define L_CH   8          // T_LEN / NCHUNK
#define NROUND 7          // log2(NCHUNK)
#define DG     4          // d-columns per scan block
#define ATHR   (NCHUNK * DG)   // 512 threads in kernel A

// Constants passed by value (computed in double on host; deterministic).
struct HippoConsts {
    float Pk[NROUND][16];      // Abar^(L_CH * 2^r)
    float Pow[L_CH][16];       // Abar^(t+1), t = 0..7
    float Wc[L_CH][4];         // Abar^m * Bbar, m = 0..7
};

// Static scratch (no allocs). B <= 8 supported.
__device__ float4 g_start[8 * NCHUNK * D_DIM];  // start-states, [b][j][d]

// v = M*p + v  (4x4 matvec-accumulate on float4, M row-major)
__device__ __forceinline__ float4 mvacc(const float* M, float4 p, float4 v) {
    float4 r;
    r.x = fmaf(M[0],  p.x, fmaf(M[1],  p.y, fmaf(M[2],  p.z, fmaf(M[3],  p.w, v.x))));
    r.y = fmaf(M[4],  p.x, fmaf(M[5],  p.y, fmaf(M[6],  p.z, fmaf(M[7],  p.w, v.y))));
    r.z = fmaf(M[8],  p.x, fmaf(M[9],  p.y, fmaf(M[10], p.z, fmaf(M[11], p.w, v.z))));
    r.w = fmaf(M[12], p.x, fmaf(M[13], p.y, fmaf(M[14], p.z, fmaf(M[15], p.w, v.w))));
    return r;
}

// v += w * s  (4-vector times scalar)
__device__ __forceinline__ float4 wfma(const float* w, float s, float4 v) {
    v.x = fmaf(w[0], s, v.x);
    v.y = fmaf(w[1], s, v.y);
    v.z = fmaf(w[2], s, v.z);
    v.w = fmaf(w[3], s, v.w);
    return v;
}

#define SSTR 5   // slab row stride in floats

// ---- Kernel A: per (b, 4-d group): parallel chunk end-states + in-block scan ----
// threads: tid = j*DG + dd (j = chunk 0..127, dd = 0..3)
__global__ __launch_bounds__(ATHR)
void hippo_scan(const float* __restrict__ h, HippoConsts c) {
    __shared__ float  sh[T_LEN * SSTR];   // slab: sh[t*5 + dd]
    __shared__ float4 s[2][ATHR];         // ping-pong scan workspace

    const int tid = threadIdx.x;
    const int g   = blockIdx.x;           // d-group (0..63)
    const int b   = blockIdx.y;
    const int d0  = g * DG;

    // stage slab: thread loads rows 2*tid, 2*tid+1 (one float4 each)
    {
        const float* hb = h + (size_t)b * T_LEN * D_DIM + d0;
        const int r0 = tid * 2;
        float4 a0 = __ldg((const float4*)(hb + (size_t)r0 * D_DIM));
        float4 a1 = __ldg((const float4*)(hb + (size_t)(r0 + 1) * D_DIM));
        float* p0 = sh + r0 * SSTR;
        p0[0] = a0.x; p0[1] = a0.y; p0[2] = a0.z; p0[3] = a0.w;
        float* p1 = sh + (r0 + 1) * SSTR;
        p1[0] = a1.x; p1[1] = a1.y; p1[2] = a1.z; p1[3] = a1.w;
    }
    __syncthreads();

    const int j  = tid >> 2;          // chunk
    const int dd = tid & 3;           // d within group
    const float* col = sh + (size_t)(j * L_CH) * SSTR + dd;

    // chunk end-state, PARALLEL form: e = sum_s Wc[7-s] * h_s (no serial chain)
    float hr[L_CH];
    #pragma unroll
    for (int t = 0; t < L_CH; t++) hr[t] = col[t * SSTR];

    float4 e0 = make_float4(0.f, 0.f, 0.f, 0.f);
    float4 e1 = make_float4(0.f, 0.f, 0.f, 0.f);
    #pragma unroll
    for (int t = 0; t < L_CH; t += 2) {
        e0 = wfma(c.Wc[L_CH - 1 - t], hr[t], e0);
        e1 = wfma(c.Wc[L_CH - 2 - t], hr[t + 1], e1);
    }
    float4 v = make_float4(e0.x + e1.x, e0.y + e1.y, e0.z + e1.z, e0.w + e1.w);

    int cur = 0;
    s[cur][tid] = v;
    __syncthreads();

    // Kogge-Stone affine scan, ping-pong buffers: ONE sync per round
    #pragma unroll
    for (int r = 0; r < NROUND; r++) {
        const int off = 1 << r;
        if (j >= off) {
            float4 prev = s[cur][tid - off * DG];
            v = mvacc(c.Pk[r], prev, v);   // v += P^(2^r) * prev
        }
        s[cur ^ 1][tid] = v;
        cur ^= 1;
        __syncthreads();
    }

    // exclusive prefix -> start states, [b][j][d] layout
    float4 st = make_float4(0.f, 0.f, 0.f, 0.f);
    if (j > 0) st = s[cur][tid - DG];
    g_start[((size_t)b * NCHUNK + j) * D_DIM + d0 + dd] = st;
}

// ---- Kernel B': closed-form outputs, zero serial dependence ----
// block = chunk j (512 thr): tid = t*64 + dg, t = step in chunk, d0 = dg*4.
// x_t = Pow[t]*xs + sum_{s<=t} Wc[t-s]*h_s   per d column.
__global__ __launch_bounds__(512)
void hippo_out(const float* __restrict__ h, float* __restrict__ out, HippoConsts c) {
    __shared__ float4 sh4[L_CH * 64];     // chunk slab: sh4[s*64 + dg] = h[s][4d]

    const int tid = threadIdx.x;
    const int j = blockIdx.x;
    const int b = blockIdx.y;
    const int t  = tid >> 6;              // 0..7
    const int dg = tid & 63;              // 0..63
    const int d0 = dg * 4;

    // stage chunk (8 rows x 256 floats = 512 float4), one load per thread
    const float4* src = (const float4*)(h + ((size_t)(b * T_LEN + j * L_CH)) * D_DIM);
    sh4[tid] = __ldg(src + tid);

    // start states for this thread's 4 d-columns (coalesced 64B/thread)
    const float4* gs = g_start + ((size_t)b * NCHUNK + j) * D_DIM + d0;
    float4 xs0 = gs[0], xs1 = gs[1], xs2 = gs[2], xs3 = gs[3];
    __syncthreads();

    // accumulators: a{i} = state vector for d0+i
    float4 a0 = make_float4(0.f, 0.f, 0.f, 0.f);
    float4 a1 = a0, a2 = a0, a3 = a0;

    // causal convolution part (trip count uniform per warp: t = tid>>6)
    for (int sgm = 0; sgm <= t; ++sgm) {
        float4 hv = sh4[sgm * 64 + dg];
        const float* w = c.Wc[t - sgm];
        a0 = wfma(w, hv.x, a0);
        a1 = wfma(w, hv.y, a1);
        a2 = wfma(w, hv.z, a2);
        a3 = wfma(w, hv.w, a3);
    }
    // start-state propagation part
    const float* M = c.Pow[t];
    a0 = mvacc(M, xs0, a0);
    a1 = mvacc(M, xs1, a1);
    a2 = mvacc(M, xs2, a2);
    a3 = mvacc(M, xs3, a3);

    // store: out[b][j*8+t][k][d0..d0+3], one float4 per k (coalesced per warp)
    float* op = out + (((size_t)b * T_LEN + j * L_CH + t) * K_CH) * D_DIM + d0;
    *(float4*)(op)              = make_float4(a0.x, a1.x, a2.x, a3.x);
    *(float4*)(op + D_DIM)      = make_float4(a0.y, a1.y, a2.y, a3.y);
    *(float4*)(op + 2 * D_DIM)  = make_float4(a0.z, a1.z, a2.z, a3.z);
    *(float4*)(op + 3 * D_DIM)  = make_float4(a0.w, a1.w, a2.w, a3.w);
}

// ---------------- host-side constant construction (double precision) ----------------

static void inv4x4(const double Min[4][4], double Mout[4][4]) {
    double a[4][8];
    for (int i = 0; i < 4; i++)
        for (int jj = 0; jj < 8; jj++)
            a[i][jj] = (jj < 4) ? Min[i][jj] : (jj - 4 == i ? 1.0 : 0.0);
    for (int col = 0; col < 4; col++) {
        int p = col;
        for (int rr = col + 1; rr < 4; rr++)
            if (fabs(a[rr][col]) > fabs(a[p][col])) p = rr;
        if (p != col)
            for (int jj = 0; jj < 8; jj++) { double t = a[col][jj]; a[col][jj] = a[p][jj]; a[p][jj] = t; }
        double piv = a[col][col];
        for (int jj = 0; jj < 8; jj++) a[col][jj] /= piv;
        for (int rr = 0; rr < 4; rr++) {
            if (rr == col) continue;
            double f = a[rr][col];
            for (int jj = 0; jj < 8; jj++) a[rr][jj] -= f * a[col][jj];
        }
    }
    for (int i = 0; i < 4; i++)
        for (int jj = 0; jj < 4; jj++)
            Mout[i][jj] = a[i][jj + 4];
}

static void matmul4(const double A[4][4], const double B[4][4], double C[4][4]) {
    for (int i = 0; i < 4; i++)
        for (int jj = 0; jj < 4; jj++) {
            double s = 0.0;
            for (int k = 0; k < 4; k++) s += A[i][k] * B[k][jj];
            C[i][jj] = s;
        }
}

extern "C" void kernel_launch(void* const* d_in, const int* in_sizes, int n_in,
                              void* d_out, int out_size) {
    const float* h;
    int sz0 = in_sizes[0], sz1 = in_sizes[1];
    if (sz0 > sz1) h = (const float*)d_in[0];
    else           h = (const float*)d_in[1];
    int hsz = (sz0 > sz1) ? sz0 : sz1;
    int B = hsz / (T_LEN * D_DIM);

    // --- HiPPO-LegT constants (matches reference _make_hippo_legt + bilinear) ---
    const double theta = 200.0;
    const double dt = 1.0 / theta;
    double A[4][4], Bv[4], Pn[4];
    for (int i = 0; i < 4; i++) Pn[i] = sqrt(2.0 * i + 1.0);
    for (int i = 0; i < 4; i++) {
        Bv[i] = Pn[i];
        for (int jj = 0; jj < 4; jj++) {
            double sg = 1.0;
            if (jj > i && ((jj - i) & 1)) sg = -1.0;   // (-1)^(j-i) upper triangle
            A[i][jj] = -Pn[i] * Pn[jj] * sg;
        }
    }
    double ImA[4][4], IpA[4][4], Inv[4][4], Abar[4][4];
    for (int i = 0; i < 4; i++)
        for (int jj = 0; jj < 4; jj++) {
            double eye = (i == jj) ? 1.0 : 0.0;
            ImA[i][jj] = eye - 0.5 * dt * A[i][jj];
            IpA[i][jj] = eye + 0.5 * dt * A[i][jj];
        }
    inv4x4(ImA, Inv);
    matmul4(Inv, IpA, Abar);
    double Bbar[4];
    for (int i = 0; i < 4; i++) {
        double sacc = 0.0;
        for (int jj = 0; jj < 4; jj++) sacc += Inv[i][jj] * Bv[jj] * dt;
        Bbar[i] = sacc;
    }

    HippoConsts c;

    // Wc[m] = Abar^m * Bbar
    double wc[L_CH][4];
    for (int i = 0; i < 4; i++) wc[0][i] = Bbar[i];
    for (int m = 1; m < L_CH; m++)
        for (int i = 0; i < 4; i++) {
            double sacc = 0.0;
            for (int jj = 0; jj < 4; jj++) sacc += Abar[i][jj] * wc[m - 1][jj];
            wc[m][i] = sacc;
        }
    for (int m = 0; m < L_CH; m++)
        for (int i = 0; i < 4; i++) c.Wc[m][i] = (float)wc[m][i];

    // Pow[t] = Abar^(t+1)
    double Cur[4][4], Tmp[4][4];
    for (int i = 0; i < 4; i++)
        for (int jj = 0; jj < 4; jj++) Cur[i][jj] = Abar[i][jj];
    for (int t = 0; t < L_CH; t++) {
        for (int i = 0; i < 16; i++) c.Pow[t][i] = (float)Cur[i / 4][i % 4];
        matmul4(Cur, Abar, Tmp);
        for (int i = 0; i < 4; i++)
            for (int jj = 0; jj < 4; jj++) Cur[i][jj] = Tmp[i][jj];
    }

    // Pk[r] = Abar^(L_CH * 2^r): Pk[0] = Abar^8, Pk[r] = Pk[r-1]^2
    double Pw[NROUND][4][4];
    for (int i = 0; i < 4; i++)
        for (int jj = 0; jj < 4; jj++) Cur[i][jj] = (i == jj) ? 1.0 : 0.0;
    for (int m = 0; m < L_CH; m++) {
        matmul4(Cur, Abar, Tmp);
        for (int i = 0; i < 4; i++)
            for (int jj = 0; jj < 4; jj++) Cur[i][jj] = Tmp[i][jj];
    }
    for (int i = 0; i < 4; i++)
        for (int jj = 0; jj < 4; jj++) Pw[0][i][jj] = Cur[i][jj];
    for (int r = 1; r < NROUND; r++) {
        matmul4(Pw[r - 1], Pw[r - 1], Tmp);
        for (int i = 0; i < 4; i++)
            for (int jj = 0; jj < 4; jj++) Pw[r][i][jj] = Tmp[i][jj];
    }
    for (int r = 0; r < NROUND; r++)
        for (int i = 0; i < 16; i++)
            c.Pk[r][i] = (float)Pw[r][i / 4][i % 4];

    dim3 gridA(D_DIM / DG, B);      // 64 x B = 128 blocks
    dim3 gridB(NCHUNK, B);          // 128 x B = 256 blocks
    hippo_scan<<<gridA, ATHR>>>(h, c);
    hippo_out<<<gridB, 512>>>(h, (float*)d_out, c);
}